// round 12
// baseline (speedup 1.0000x reference)
#include <cuda_runtime.h>
#include <stdint.h>

#define N_RES 1024
#define C_M   256
#define C_Z   128
#define NUM_BINS 15
#define EPS 1e-5f
#define INF_F 1e8f

#define Z_BLOCKS 32768   // 32768 blocks * 8 warps * 4 rows = 1,048,576 rows
#define M_BLOCKS 128     // 128 blocks * 8 warps = 1024 m-rows

// Scratch: folded add-table (ln_z_b + lin_b + lin_w[:,bin]; row 15 = no bin),
// and packed x coordinates.
__device__ float  g_table[(NUM_BINS + 1) * C_Z];
__device__ float4 g_x4[N_RES];

// ---------------------------------------------------------------------------
// Tiny pre-kernel (1 block): build g_table and g_x4.
// ---------------------------------------------------------------------------
__global__ void __launch_bounds__(256) table_kernel(
        const float* __restrict__ x,
        const float* __restrict__ zb,      // ln_z_b
        const float* __restrict__ lin_w,   // [C_Z, NUM_BINS]
        const float* __restrict__ lin_b) { // [C_Z]
    int tid = threadIdx.x;
    for (int idx = tid; idx < (NUM_BINS + 1) * C_Z; idx += 256) {
        int bin = idx >> 7;          // 0..15
        int c   = idx & (C_Z - 1);
        float v = zb[c] + lin_b[c];
        if (bin < NUM_BINS) v += lin_w[c * NUM_BINS + bin];
        g_table[idx] = v;
    }
    for (int n = tid; n < N_RES; n += 256) {
        g_x4[n] = make_float4(x[3*n], x[3*n+1], x[3*n+2], 0.0f);
    }
}

// Exact squared bin boundary (compile-time constants after unroll)
__device__ __forceinline__ float sqb(int k) {
    float b = 3.25f + 1.25f * k;
    return b * b;
}

// Candidate-verified bin index into g_table (NUM_BINS = no bin).
// Result identical to the reference 15-compare loop.
__device__ __forceinline__ int find_bin_idx(float d2) {
    float t = (sqrtf(d2) - 3.25f) * 0.8f;
    int kc = (int)floorf(t);
    kc = max(0, min(NUM_BINS - 1, kc));
    int bin = NUM_BINS;
    #pragma unroll
    for (int dk = -1; dk <= 1; dk++) {
        int k = kc + dk;
        if (k >= 0 && k < NUM_BINS) {
            float lo = sqb(k);
            float hi = (k < NUM_BINS - 1) ? sqb(k + 1) : INF_F;
            if (d2 > lo && d2 < hi) bin = k;
        }
    }
    return bin;
}

// ---------------------------------------------------------------------------
// Main kernel:
//   blocks [0, Z_BLOCKS):             z_update, one warp per FOUR rows (same i)
//   blocks [Z_BLOCKS, Z_BLOCKS+128):  m_update LayerNorm, one warp per row
// ---------------------------------------------------------------------------
__global__ void __launch_bounds__(256) main_kernel(
        const float* __restrict__ z,
        const float* __restrict__ w,       // ln_z_w
        const float* __restrict__ m,
        const float* __restrict__ mw,
        const float* __restrict__ mb,
        float* __restrict__ out_z,
        float* __restrict__ out_m) {
    int wid  = threadIdx.x >> 5;
    int lane = threadIdx.x & 31;

    if (blockIdx.x >= Z_BLOCKS) {
        // ---- m LayerNorm: one warp per row of [1024, 256] ----
        int row_i = (blockIdx.x - Z_BLOCKS) * 8 + wid;
        const float4* row = reinterpret_cast<const float4*>(m + (size_t)row_i * C_M);
        float4 v0 = row[lane];
        float4 v1 = row[lane + 32];

        float s  = v0.x + v0.y + v0.z + v0.w + v1.x + v1.y + v1.z + v1.w;
        float ss = v0.x*v0.x + v0.y*v0.y + v0.z*v0.z + v0.w*v0.w
                 + v1.x*v1.x + v1.y*v1.y + v1.z*v1.z + v1.w*v1.w;
        #pragma unroll
        for (int off = 16; off > 0; off >>= 1) {
            s  += __shfl_xor_sync(0xFFFFFFFFu, s,  off);
            ss += __shfl_xor_sync(0xFFFFFFFFu, ss, off);
        }
        float mu   = s * (1.0f / C_M);
        float rstd = rsqrtf(ss * (1.0f / C_M) - mu * mu + EPS);

        const float4* wv = reinterpret_cast<const float4*>(mw);
        const float4* bv = reinterpret_cast<const float4*>(mb);
        float4 w0 = wv[lane], w1 = wv[lane + 32];
        float4 b0 = bv[lane], b1 = bv[lane + 32];

        float4 o0, o1;
        o0.x = (v0.x - mu) * rstd * w0.x + b0.x;
        o0.y = (v0.y - mu) * rstd * w0.y + b0.y;
        o0.z = (v0.z - mu) * rstd * w0.z + b0.z;
        o0.w = (v0.w - mu) * rstd * w0.w + b0.w;
        o1.x = (v1.x - mu) * rstd * w1.x + b1.x;
        o1.y = (v1.y - mu) * rstd * w1.y + b1.y;
        o1.z = (v1.z - mu) * rstd * w1.z + b1.z;
        o1.w = (v1.w - mu) * rstd * w1.w + b1.w;

        float4* orow = reinterpret_cast<float4*>(out_m + (size_t)row_i * C_M);
        orow[lane]      = o0;
        orow[lane + 32] = o1;
        return;
    }

    // ---- z path: one warp per FOUR consecutive rows (same i) ----
    int warp = blockIdx.x * 8 + wid;       // 0 .. 262143
    int r0   = warp << 2;                  // first of 4 rows
    int i    = r0 >> 10;
    int j0   = r0 & (N_RES - 1);

    // front-batched loads: four z rows, MLP=4 per lane
    const float4* zrow = reinterpret_cast<const float4*>(z + (size_t)r0 * C_Z);
    float4 v0 = zrow[lane];
    float4 v1 = zrow[lane + 32];
    float4 v2 = zrow[lane + 64];
    float4 v3 = zrow[lane + 96];

    // warp-uniform x loads
    float4 xi  = g_x4[i];
    float4 xj0 = g_x4[j0];
    float4 xj1 = g_x4[j0 + 1];
    float4 xj2 = g_x4[j0 + 2];
    float4 xj3 = g_x4[j0 + 3];

    // per-row sums
    float s0  = v0.x + v0.y + v0.z + v0.w;
    float q0  = v0.x*v0.x + v0.y*v0.y + v0.z*v0.z + v0.w*v0.w;
    float s1  = v1.x + v1.y + v1.z + v1.w;
    float q1  = v1.x*v1.x + v1.y*v1.y + v1.z*v1.z + v1.w*v1.w;
    float s2  = v2.x + v2.y + v2.z + v2.w;
    float q2  = v2.x*v2.x + v2.y*v2.y + v2.z*v2.z + v2.w*v2.w;
    float s3  = v3.x + v3.y + v3.z + v3.w;
    float q3  = v3.x*v3.x + v3.y*v3.y + v3.z*v3.z + v3.w*v3.w;

    #pragma unroll
    for (int off = 16; off > 0; off >>= 1) {
        s0 += __shfl_xor_sync(0xFFFFFFFFu, s0, off);
        q0 += __shfl_xor_sync(0xFFFFFFFFu, q0, off);
        s1 += __shfl_xor_sync(0xFFFFFFFFu, s1, off);
        q1 += __shfl_xor_sync(0xFFFFFFFFu, q1, off);
        s2 += __shfl_xor_sync(0xFFFFFFFFu, s2, off);
        q2 += __shfl_xor_sync(0xFFFFFFFFu, q2, off);
        s3 += __shfl_xor_sync(0xFFFFFFFFu, s3, off);
        q3 += __shfl_xor_sync(0xFFFFFFFFu, q3, off);
    }
    float mu0 = s0 * (1.0f / C_Z), r0s = rsqrtf(q0 * (1.0f / C_Z) - mu0*mu0 + EPS);
    float mu1 = s1 * (1.0f / C_Z), r1s = rsqrtf(q1 * (1.0f / C_Z) - mu1*mu1 + EPS);
    float mu2 = s2 * (1.0f / C_Z), r2s = rsqrtf(q2 * (1.0f / C_Z) - mu2*mu2 + EPS);
    float mu3 = s3 * (1.0f / C_Z), r3s = rsqrtf(q3 * (1.0f / C_Z) - mu3*mu3 + EPS);

    // distances + table indices
    float dx, dy, dz2;
    dx = xi.x - xj0.x; dy = xi.y - xj0.y; dz2 = xi.z - xj0.z;
    int idx0 = find_bin_idx(dx*dx + dy*dy + dz2*dz2);
    dx = xi.x - xj1.x; dy = xi.y - xj1.y; dz2 = xi.z - xj1.z;
    int idx1 = find_bin_idx(dx*dx + dy*dy + dz2*dz2);
    dx = xi.x - xj2.x; dy = xi.y - xj2.y; dz2 = xi.z - xj2.z;
    int idx2 = find_bin_idx(dx*dx + dy*dy + dz2*dz2);
    dx = xi.x - xj3.x; dy = xi.y - xj3.y; dz2 = xi.z - xj3.z;
    int idx3 = find_bin_idx(dx*dx + dy*dy + dz2*dz2);

    // table rows, dedup against row 0 (warp-uniform predicates)
    const float4* tbl = reinterpret_cast<const float4*>(g_table);
    float4 t0 = __ldg(&tbl[idx0 * (C_Z / 4) + lane]);
    float4 t1 = (idx1 == idx0) ? t0 : __ldg(&tbl[idx1 * (C_Z / 4) + lane]);
    float4 t2 = (idx2 == idx0) ? t0 : ((idx2 == idx1) ? t1 : __ldg(&tbl[idx2 * (C_Z / 4) + lane]));
    float4 t3 = (idx3 == idx0) ? t0 : ((idx3 == idx1) ? t1 : ((idx3 == idx2) ? t2 : __ldg(&tbl[idx3 * (C_Z / 4) + lane])));

    float4 wr = __ldg(&reinterpret_cast<const float4*>(w)[lane]);

    float4 o;
    float4* orow = reinterpret_cast<float4*>(out_z + (size_t)r0 * C_Z);

    o.x = (v0.x - mu0) * r0s * wr.x + t0.x;
    o.y = (v0.y - mu0) * r0s * wr.y + t0.y;
    o.z = (v0.z - mu0) * r0s * wr.z + t0.z;
    o.w = (v0.w - mu0) * r0s * wr.w + t0.w;
    orow[lane] = o;

    o.x = (v1.x - mu1) * r1s * wr.x + t1.x;
    o.y = (v1.y - mu1) * r1s * wr.y + t1.y;
    o.z = (v1.z - mu1) * r1s * wr.z + t1.z;
    o.w = (v1.w - mu1) * r1s * wr.w + t1.w;
    orow[lane + 32] = o;

    o.x = (v2.x - mu2) * r2s * wr.x + t2.x;
    o.y = (v2.y - mu2) * r2s * wr.y + t2.y;
    o.z = (v2.z - mu2) * r2s * wr.z + t2.z;
    o.w = (v2.w - mu2) * r2s * wr.w + t2.w;
    orow[lane + 64] = o;

    o.x = (v3.x - mu3) * r3s * wr.x + t3.x;
    o.y = (v3.y - mu3) * r3s * wr.y + t3.y;
    o.z = (v3.z - mu3) * r3s * wr.z + t3.z;
    o.w = (v3.w - mu3) * r3s * wr.w + t3.w;
    orow[lane + 96] = o;
}

// ---------------------------------------------------------------------------
// Launch
// Inputs: m, z, x, ln_m_w, ln_m_b, ln_z_w, ln_z_b, lin_w, lin_b
// Output: m_update [1024*256] then z_update [1024*1024*128]
// ---------------------------------------------------------------------------
extern "C" void kernel_launch(void* const* d_in, const int* in_sizes, int n_in,
                              void* d_out, int out_size) {
    const float* m      = (const float*)d_in[0];
    const float* z      = (const float*)d_in[1];
    const float* x      = (const float*)d_in[2];
    const float* ln_m_w = (const float*)d_in[3];
    const float* ln_m_b = (const float*)d_in[4];
    const float* ln_z_w = (const float*)d_in[5];
    const float* ln_z_b = (const float*)d_in[6];
    const float* lin_w  = (const float*)d_in[7];
    const float* lin_b  = (const float*)d_in[8];

    float* out_m = (float*)d_out;
    float* out_z = out_m + (size_t)N_RES * C_M;

    // 1 block: build folded table + packed x
    table_kernel<<<1, 256>>>(x, ln_z_b, lin_w, lin_b);

    // z (4 rows/warp) + fused m-LN
    main_kernel<<<Z_BLOCKS + M_BLOCKS, 256>>>(z, ln_z_w, m, ln_m_w, ln_m_b,
                                              out_z, out_m);
}